// round 17
// baseline (speedup 1.0000x reference)
#include <cuda_runtime.h>
#include <cuda_fp16.h>
#include <cuda_bf16.h>
#include <mma.h>
#include <math.h>

using namespace nvcuda;

// Problem constants (fixed by the dataset)
#define NNODES 100000
#define MAXE   1600000
#define NFEAT  128
#define NHID   64
#define NCLASS 16

// Scratch buffers.
__device__ __align__(128) uint4  g_sup1h[NNODES * 8];   // N x 64 fp16 (x @ W1)
__device__ __align__(128) __half g_sup2h[NNODES * 16];  // N x 16 fp16 (h @ W2)
__device__ __align__(128) int g_work[NNODES + 128];     // [0,N): cnt/cursor, [N,N+128): scan aggs
__device__ int  g_off[NNODES + 1];   // CSR offsets
__device__ int2 g_csr[MAXE];         // packed {src, float_as_int(w)}

// ---------------------------------------------------------------------------
// GEMM1 (HMMA): sup1[N,64] = x[N,128] @ W1[128,64], fp16 in, fp32 acc,
// fp16 out. 128x64 block tile, KC=64 (2 phases), 8 warps, warp = 16 rows.
// ---------------------------------------------------------------------------
__global__ void __launch_bounds__(256) gemm1_kernel(
        const float* __restrict__ x,
        const float* __restrict__ W1,
        uint4* __restrict__ outh, int N) {
    __shared__ __align__(16) char smem[32768];
    __half (*sA)[72] = (__half(*)[72])smem;                  // 128 x 72 halves
    __half (*sB)[72] = (__half(*)[72])(smem + 128 * 72 * 2); // 64 x 72 halves
    float (*sO)[64]  = (float(*)[64])smem;                   // epilogue alias

    int tid = threadIdx.x;
    int w = tid >> 5;
    int lane = tid & 31;
    int rb = blockIdx.x * 128;

    wmma::fragment<wmma::accumulator, 16, 16, 16, float> acc[4];
#pragma unroll
    for (int i = 0; i < 4; i++) wmma::fill_fragment(acc[i], 0.f);

#pragma unroll
    for (int kb = 0; kb < NFEAT; kb += 64) {
#pragma unroll
        for (int it = 0; it < 8; it++) {
            int idx = tid + it * 256;
            int row = idx >> 4;
            int cc = (idx & 15) * 4;
            float4 v = make_float4(0.f, 0.f, 0.f, 0.f);
            if (rb + row < N)
                v = *(const float4*)&x[(size_t)(rb + row) * NFEAT + kb + cc];
            *(__half2*)&sA[row][cc]     = __floats2half2_rn(v.x, v.y);
            *(__half2*)&sA[row][cc + 2] = __floats2half2_rn(v.z, v.w);
        }
#pragma unroll
        for (int it = 0; it < 4; it++) {
            int idx = tid + it * 256;
            int row = idx >> 4;
            int cc = (idx & 15) * 4;
            float4 v = *(const float4*)&W1[(size_t)(kb + row) * NHID + cc];
            *(__half2*)&sB[row][cc]     = __floats2half2_rn(v.x, v.y);
            *(__half2*)&sB[row][cc + 2] = __floats2half2_rn(v.z, v.w);
        }
        __syncthreads();

#pragma unroll
        for (int ks = 0; ks < 64; ks += 16) {
            wmma::fragment<wmma::matrix_a, 16, 16, 16, __half, wmma::row_major> fa;
            wmma::load_matrix_sync(fa, &sA[w * 16][ks], 72);
#pragma unroll
            for (int nt = 0; nt < 4; nt++) {
                wmma::fragment<wmma::matrix_b, 16, 16, 16, __half, wmma::row_major> fb;
                wmma::load_matrix_sync(fb, &sB[ks][nt * 16], 72);
                wmma::mma_sync(acc[nt], fa, fb, acc[nt]);
            }
        }
        __syncthreads();
    }

#pragma unroll
    for (int nt = 0; nt < 4; nt++)
        wmma::store_matrix_sync(&sO[w * 16][nt * 16], acc[nt], 64, wmma::mem_row_major);
    __syncwarp();

#pragma unroll
    for (int q = 0; q < 4; q++) {
        int idx = lane + q * 32;
        int r = idx >> 3;
        int c8 = idx & 7;
        int row = rb + w * 16 + r;
        if (row < N) {
            const float* p = &sO[w * 16 + r][c8 * 8];
            __half2 h0 = __floats2half2_rn(p[0], p[1]);
            __half2 h1 = __floats2half2_rn(p[2], p[3]);
            __half2 h2 = __floats2half2_rn(p[4], p[5]);
            __half2 h3 = __floats2half2_rn(p[6], p[7]);
            uint4 o;
            o.x = *(unsigned*)&h0; o.y = *(unsigned*)&h1;
            o.z = *(unsigned*)&h2; o.w = *(unsigned*)&h3;
            outh[(size_t)row * 8 + c8] = o;
        }
    }
}

// ---------------------------------------------------------------------------
// CSR build
// ---------------------------------------------------------------------------
// Histogram: 4 consecutive edges per thread via one LDG.128.
__global__ void __launch_bounds__(256) hist_kernel(
        const int* __restrict__ dst, int* __restrict__ cnt, int E) {
    int e4 = (blockIdx.x * blockDim.x + threadIdx.x) * 4;
    if (e4 + 3 < E) {
        int4 d = *(const int4*)&dst[e4];
        atomicAdd(&cnt[d.x], 1);
        atomicAdd(&cnt[d.y], 1);
        atomicAdd(&cnt[d.z], 1);
        atomicAdd(&cnt[d.w], 1);
    } else {
        for (int e = e4; e < E; e++) atomicAdd(&cnt[dst[e]], 1);
    }
}

// Fused exclusive scan with decoupled lookback (98 blocks). Also initializes
// the permute cursor. Deadlock-free: blocks only wait on lower block ids.
__global__ void __launch_bounds__(1024) scan_fused(
        const int* __restrict__ cnt,
        int* __restrict__ off,
        int* __restrict__ cursor,
        volatile int* __restrict__ aggp,   // zeroed before launch; agg+1
        int n, int E) {
    __shared__ int s[1024];
    __shared__ int s_prefix;
    int b = blockIdx.x;
    int i = b * 1024 + threadIdx.x;
    int v = (i < n) ? cnt[i] : 0;
    s[threadIdx.x] = v;
    __syncthreads();
#pragma unroll
    for (int d = 1; d < 1024; d <<= 1) {
        int t = (threadIdx.x >= d) ? s[threadIdx.x - d] : 0;
        __syncthreads();
        s[threadIdx.x] += t;
        __syncthreads();
    }
    int local_excl = s[threadIdx.x] - v;
    int total = s[1023];

    if (threadIdx.x == 0) {
        __threadfence();
        aggp[b] = total + 1;
    }

    int contrib = 0;
    if (threadIdx.x < (unsigned)b) {
        int a;
        do { a = aggp[threadIdx.x]; } while (a == 0);
        contrib = a - 1;
    }
    __syncthreads();
    s[threadIdx.x] = contrib;
    __syncthreads();
#pragma unroll
    for (int d = 512; d; d >>= 1) {
        if (threadIdx.x < d) s[threadIdx.x] += s[threadIdx.x + d];
        __syncthreads();
    }
    if (threadIdx.x == 0) s_prefix = s[0];
    __syncthreads();
    int prefix = s_prefix;

    if (i < n) {
        int o = local_excl + prefix;
        off[i] = o;
        cursor[i] = o;
    }
    if (i == 0) off[n] = E;
}

// Permute: 4 consecutive edges per thread via 3x LDG.128.
__global__ void __launch_bounds__(256) permute_kernel(
        const int* __restrict__ src,
        const int* __restrict__ dst,
        const float* __restrict__ ew,
        int* __restrict__ cursor,
        int2* __restrict__ csr, int E) {
    int e4 = (blockIdx.x * blockDim.x + threadIdx.x) * 4;
    if (e4 + 3 < E) {
        int4 d = *(const int4*)&dst[e4];
        int4 s = *(const int4*)&src[e4];
        float4 w = *(const float4*)&ew[e4];
        int p0 = atomicAdd(&cursor[d.x], 1);
        int p1 = atomicAdd(&cursor[d.y], 1);
        int p2 = atomicAdd(&cursor[d.z], 1);
        int p3 = atomicAdd(&cursor[d.w], 1);
        csr[p0] = make_int2(s.x, __float_as_int(w.x));
        csr[p1] = make_int2(s.y, __float_as_int(w.y));
        csr[p2] = make_int2(s.z, __float_as_int(w.z));
        csr[p3] = make_int2(s.w, __float_as_int(w.w));
    } else {
        for (int e = e4; e < E; e++) {
            int p = atomicAdd(&cursor[dst[e]], 1);
            csr[p] = make_int2(src[e], __float_as_int(ew[e]));
        }
    }
}

// ---------------------------------------------------------------------------
// Gather stage 1 (fused): 8 lanes per edge — lane loads uint4 (16B = 8
// halves) of the 128B fp16 row; warp processes 4 edges concurrently, x2
// unroll -> 8 gathers in flight. Then h = relu(agg+b1), sup2 = fp16(h@W2).
// ---------------------------------------------------------------------------
__global__ void __launch_bounds__(256) gather1_kernel(
        const int* __restrict__ off,
        const int2* __restrict__ csr,
        const uint4* __restrict__ suph4,   // N x 8 uint4 rows
        const float* __restrict__ b1,
        const float* __restrict__ W2,
        __half* __restrict__ sup2h, int N) {
    __shared__ float sW[NHID * NCLASS];  // 4 KB
    __shared__ float sb[NHID];
    __shared__ __align__(16) float sh[8][NHID];  // per-warp h row
    for (int i = threadIdx.x; i < NHID * NCLASS; i += blockDim.x) sW[i] = W2[i];
    if (threadIdx.x < NHID) sb[threadIdx.x] = b1[threadIdx.x];
    __syncthreads();

    int warp = (blockIdx.x * blockDim.x + threadIdx.x) >> 5;
    int wid = (threadIdx.x >> 5);
    int lane = threadIdx.x & 31;
    if (warp >= N) return;
    int g8 = lane >> 3;      // edge slot (0..3)
    int l8 = lane & 7;       // covers hid values 8*l8 .. 8*l8+7

    int beg = off[warp], end = off[warp + 1];
    float a[8];
#pragma unroll
    for (int k = 0; k < 8; k++) a[k] = 0.f;

    int j = beg + g8;
    for (; j + 4 < end; j += 8) {      // 2 edges for this 8-lane group
        int2 ea = csr[j];
        int2 eb = csr[j + 4];
        uint4 ua = suph4[(size_t)ea.x * 8 + l8];
        uint4 ub = suph4[(size_t)eb.x * 8 + l8];
        float wa = __int_as_float(ea.y), wb = __int_as_float(eb.y);
        float2 f;
        f = __half22float2(*(__half2*)&ua.x); a[0] += wa * f.x; a[1] += wa * f.y;
        f = __half22float2(*(__half2*)&ua.y); a[2] += wa * f.x; a[3] += wa * f.y;
        f = __half22float2(*(__half2*)&ua.z); a[4] += wa * f.x; a[5] += wa * f.y;
        f = __half22float2(*(__half2*)&ua.w); a[6] += wa * f.x; a[7] += wa * f.y;
        f = __half22float2(*(__half2*)&ub.x); a[0] += wb * f.x; a[1] += wb * f.y;
        f = __half22float2(*(__half2*)&ub.y); a[2] += wb * f.x; a[3] += wb * f.y;
        f = __half22float2(*(__half2*)&ub.z); a[4] += wb * f.x; a[5] += wb * f.y;
        f = __half22float2(*(__half2*)&ub.w); a[6] += wb * f.x; a[7] += wb * f.y;
    }
    for (; j < end; j += 4) {
        int2 ed = csr[j];
        uint4 u = suph4[(size_t)ed.x * 8 + l8];
        float w = __int_as_float(ed.y);
        float2 f;
        f = __half22float2(*(__half2*)&u.x); a[0] += w * f.x; a[1] += w * f.y;
        f = __half22float2(*(__half2*)&u.y); a[2] += w * f.x; a[3] += w * f.y;
        f = __half22float2(*(__half2*)&u.z); a[4] += w * f.x; a[5] += w * f.y;
        f = __half22float2(*(__half2*)&u.w); a[6] += w * f.x; a[7] += w * f.y;
    }
    // Combine the 4 edge-slot groups (lanes 0-7 end with totals).
#pragma unroll
    for (int k = 0; k < 8; k++) {
        a[k] += __shfl_down_sync(0xffffffffu, a[k], 16);
        a[k] += __shfl_down_sync(0xffffffffu, a[k], 8);
    }
    if (lane < 8) {
        float4 h0 = make_float4(fmaxf(a[0] + sb[8 * l8 + 0], 0.f),
                                fmaxf(a[1] + sb[8 * l8 + 1], 0.f),
                                fmaxf(a[2] + sb[8 * l8 + 2], 0.f),
                                fmaxf(a[3] + sb[8 * l8 + 3], 0.f));
        float4 h1 = make_float4(fmaxf(a[4] + sb[8 * l8 + 4], 0.f),
                                fmaxf(a[5] + sb[8 * l8 + 5], 0.f),
                                fmaxf(a[6] + sb[8 * l8 + 6], 0.f),
                                fmaxf(a[7] + sb[8 * l8 + 7], 0.f));
        *(float4*)&sh[wid][8 * l8]     = h0;
        *(float4*)&sh[wid][8 * l8 + 4] = h1;
    }
    __syncwarp();

    // Projection: lanes 0-15 take even k, 16-31 odd k; c = lane & 15.
    int c = lane & 15;
    int kh = lane >> 4;
    float acc = 0.f;
#pragma unroll
    for (int i = 0; i < 32; i++) {
        int k = 2 * i + kh;
        acc += sh[wid][k] * sW[k * NCLASS + c];
    }
    acc += __shfl_down_sync(0xffffffffu, acc, 16);
    if (lane < 16) sup2h[(size_t)warp * NCLASS + lane] = __float2half_rn(acc);
}

// ---------------------------------------------------------------------------
// Gather stage 2 (fused): 4 lanes per edge — lane loads uint2 (4 classes);
// 8 edges/warp concurrently, x2 unroll -> 16 in flight. Then +b2 and
// 16-wide log_softmax across 4 lanes x 4 values.
// ---------------------------------------------------------------------------
__global__ void __launch_bounds__(256) gather2_kernel(
        const int* __restrict__ off,
        const int2* __restrict__ csr,
        const __half* __restrict__ sup2h,
        const float* __restrict__ b2,
        float* __restrict__ out, int N) {
    int warp = (blockIdx.x * blockDim.x + threadIdx.x) >> 5;
    int lane = threadIdx.x & 31;
    if (warp >= N) return;
    int g4 = lane >> 2;     // edge slot (0..7)
    int l4 = lane & 3;      // classes 4*l4 .. 4*l4+3

    int beg = off[warp], end = off[warp + 1];
    float a0 = 0.f, a1 = 0.f, a2 = 0.f, a3 = 0.f;
    int j = beg + g4;
    for (; j + 8 < end; j += 16) {     // 2 edges for this 4-lane group
        int2 ea = csr[j];
        int2 eb = csr[j + 8];
        uint2 ua = *(const uint2*)&sup2h[(size_t)ea.x * NCLASS + l4 * 4];
        uint2 ub = *(const uint2*)&sup2h[(size_t)eb.x * NCLASS + l4 * 4];
        float wa = __int_as_float(ea.y), wb = __int_as_float(eb.y);
        float2 f;
        f = __half22float2(*(__half2*)&ua.x); a0 += wa * f.x; a1 += wa * f.y;
        f = __half22float2(*(__half2*)&ua.y); a2 += wa * f.x; a3 += wa * f.y;
        f = __half22float2(*(__half2*)&ub.x); a0 += wb * f.x; a1 += wb * f.y;
        f = __half22float2(*(__half2*)&ub.y); a2 += wb * f.x; a3 += wb * f.y;
    }
    for (; j < end; j += 8) {
        int2 ed = csr[j];
        uint2 u = *(const uint2*)&sup2h[(size_t)ed.x * NCLASS + l4 * 4];
        float w = __int_as_float(ed.y);
        float2 f;
        f = __half22float2(*(__half2*)&u.x); a0 += w * f.x; a1 += w * f.y;
        f = __half22float2(*(__half2*)&u.y); a2 += w * f.x; a3 += w * f.y;
    }
    // Combine the 8 edge-slot groups (lanes 0-3 end with totals).
    a0 += __shfl_down_sync(0xffffffffu, a0, 16);
    a1 += __shfl_down_sync(0xffffffffu, a1, 16);
    a2 += __shfl_down_sync(0xffffffffu, a2, 16);
    a3 += __shfl_down_sync(0xffffffffu, a3, 16);
    a0 += __shfl_down_sync(0xffffffffu, a0, 8);
    a1 += __shfl_down_sync(0xffffffffu, a1, 8);
    a2 += __shfl_down_sync(0xffffffffu, a2, 8);
    a3 += __shfl_down_sync(0xffffffffu, a3, 8);
    a0 += __shfl_down_sync(0xffffffffu, a0, 4);
    a1 += __shfl_down_sync(0xffffffffu, a1, 4);
    a2 += __shfl_down_sync(0xffffffffu, a2, 4);
    a3 += __shfl_down_sync(0xffffffffu, a3, 4);

    float4 bb = *(const float4*)&b2[l4 * 4];
    float v0 = a0 + bb.x;
    float v1 = a1 + bb.y;
    float v2 = a2 + bb.z;
    float v3 = a3 + bb.w;
    // 16-wide log_softmax across 4 lanes x 4 values (xor within lanes 0-3).
    float m = fmaxf(fmaxf(v0, v1), fmaxf(v2, v3));
#pragma unroll
    for (int d = 2; d; d >>= 1) m = fmaxf(m, __shfl_xor_sync(0xffffffffu, m, d));
    float ex = expf(v0 - m) + expf(v1 - m) + expf(v2 - m) + expf(v3 - m);
#pragma unroll
    for (int d = 2; d; d >>= 1) ex += __shfl_xor_sync(0xffffffffu, ex, d);
    float lse = m + logf(ex);
    if (lane < 4)
        *(float4*)&out[(size_t)warp * NCLASS + l4 * 4] =
            make_float4(v0 - lse, v1 - lse, v2 - lse, v3 - lse);
}

extern "C" void kernel_launch(void* const* d_in, const int* in_sizes, int n_in,
                              void* d_out, int out_size) {
    const float* x  = (const float*)d_in[0];
    const int*   src = (const int*)d_in[1];
    const int*   dst = (const int*)d_in[2];
    const float* ew  = (const float*)d_in[3];
    const float* W1  = (const float*)d_in[4];
    const float* b1  = (const float*)d_in[5];
    const float* W2  = (const float*)d_in[6];
    const float* b2  = (const float*)d_in[7];
    float* out = (float*)d_out;

    int N = in_sizes[0] / NFEAT;   // 100000
    int E = in_sizes[1];           // 1600000

    void *p_sup1h, *p_sup2h, *p_work, *p_off, *p_csr;
    cudaGetSymbolAddress(&p_sup1h, g_sup1h);
    cudaGetSymbolAddress(&p_sup2h, g_sup2h);
    cudaGetSymbolAddress(&p_work, g_work);
    cudaGetSymbolAddress(&p_off, g_off);
    cudaGetSymbolAddress(&p_csr, g_csr);

    int* p_cnt = (int*)p_work;             // [0, N)
    int* p_agg = ((int*)p_work) + N;       // [N, N+128)

    int nb_scan = (N + 1023) / 1024;   // 98

    // Fork: gemm1 on a side stream, overlapped with the CSR build.
    cudaStream_t s1;
    cudaStreamCreateWithFlags(&s1, cudaStreamNonBlocking);
    cudaEvent_t e0, e1;
    cudaEventCreateWithFlags(&e0, cudaEventDisableTiming);
    cudaEventCreateWithFlags(&e1, cudaEventDisableTiming);

    cudaEventRecord(e0, 0);
    cudaStreamWaitEvent(s1, e0, 0);
    gemm1_kernel<<<(N + 127) / 128, 256, 0, s1>>>(x, W1, (uint4*)p_sup1h, N);
    cudaEventRecord(e1, s1);

    // --- CSR build (main stream) ---
    cudaMemsetAsync(p_work, 0, (size_t)(N + 128) * sizeof(int));  // cnt + aggs
    {
        int q = (E + 3) / 4;
        hist_kernel<<<(q + 255) / 256, 256>>>(dst, p_cnt, E);
    }
    scan_fused<<<nb_scan, 1024>>>((const int*)p_cnt, (int*)p_off, p_cnt,
                                  (volatile int*)p_agg, N, E);
    {
        int q = (E + 3) / 4;
        permute_kernel<<<(q + 255) / 256, 256>>>(src, dst, ew, p_cnt,
                                                 (int2*)p_csr, E);
    }

    // Join: gathers need both CSR and sup1.
    cudaStreamWaitEvent(0, e1, 0);

    gather1_kernel<<<(N * 32 + 255) / 256, 256>>>(
        (const int*)p_off, (const int2*)p_csr, (const uint4*)p_sup1h,
        b1, W2, (__half*)p_sup2h, N);

    gather2_kernel<<<(N * 32 + 255) / 256, 256>>>(
        (const int*)p_off, (const int2*)p_csr, (const __half*)p_sup2h,
        b2, out, N);
}